// round 15
// baseline (speedup 1.0000x reference)
#include <cuda_runtime.h>
#include <cuda_bf16.h>

#define BDIM 256
#define S_LEN 4096
#define B_ROWS 4096

__device__ float        g_accum = 0.0f;
__device__ unsigned int g_count = 0;

__device__ __forceinline__ float ex2_approx(float x) {
    float r; asm("ex2.approx.f32 %0, %1;" : "=f"(r) : "f"(x)); return r;
}
__device__ __forceinline__ float lg2_approx(float x) {
    float r; asm("lg2.approx.f32 %0, %1;" : "=f"(r) : "f"(x)); return r;
}
__device__ __forceinline__ unsigned opaque_zero(unsigned v) {
    unsigned z;
    asm volatile("and.b32 %0, %1, 0;" : "=r"(z) : "r"(v));
    return z;
}

struct F8 { float v[8]; };
struct U8 { unsigned v[8]; };
__device__ __forceinline__ F8 ldg_f8_keep(const float* p) {
    F8 r;
    asm volatile(
        "ld.global.nc.L2::evict_last.v8.b32 {%0,%1,%2,%3,%4,%5,%6,%7}, [%8];"
        : "=f"(r.v[0]), "=f"(r.v[1]), "=f"(r.v[2]), "=f"(r.v[3]),
          "=f"(r.v[4]), "=f"(r.v[5]), "=f"(r.v[6]), "=f"(r.v[7])
        : "l"(p));
    return r;
}
__device__ __forceinline__ U8 ldg_u8_stream(const int* p) {
    U8 r;
    asm volatile(
        "ld.global.nc.L2::evict_first.v8.b32 {%0,%1,%2,%3,%4,%5,%6,%7}, [%8];"
        : "=r"(r.v[0]), "=r"(r.v[1]), "=r"(r.v[2]), "=r"(r.v[3]),
          "=r"(r.v[4]), "=r"(r.v[5]), "=r"(r.v[6]), "=r"(r.v[7])
        : "l"(p));
    return r;
}

__global__ __launch_bounds__(BDIM, 4) void mtcut_row_kernel(
    const float* __restrict__ cut_y,
    const int*   __restrict__ cut_label,
    const float* __restrict__ rerank_y,
    float* __restrict__ out)
{
    const int b    = blockIdx.x;
    const int t    = threadIdx.x;
    const int lane = t & 31;
    const int wid  = t >> 5;
    const int sub  = t & 127;          // index within role half

    __shared__ float s_lg2[4];         // y-half warp partials
    __shared__ float s_es[4];          // label-half warp partials
    __shared__ int   s_ws[4];          // label-half warp scan sums

    if (wid < 4) {
        // ================= y-half: barrier-free streaming =================
        const float* p = cut_y + (size_t)b * S_LEN + sub * 32;   // 128B/thread
        F8 a = ldg_f8_keep(p);
        F8 c = ldg_f8_keep(p + 8);
        F8 d = ldg_f8_keep(p + 16);
        F8 e = ldg_f8_keep(p + 24);

        // log(prod) per 8 values (prod >= 1e-32 > FLT_MIN; y in (1e-4,1))
        float pa = ((a.v[0]*a.v[1])*(a.v[2]*a.v[3]))*((a.v[4]*a.v[5])*(a.v[6]*a.v[7]));
        float pc = ((c.v[0]*c.v[1])*(c.v[2]*c.v[3]))*((c.v[4]*c.v[5])*(c.v[6]*c.v[7]));
        float pd = ((d.v[0]*d.v[1])*(d.v[2]*d.v[3]))*((d.v[4]*d.v[5])*(d.v[6]*d.v[7]));
        float pe = ((e.v[0]*e.v[1])*(e.v[2]*e.v[3]))*((e.v[4]*e.v[5])*(e.v[6]*e.v[7]));
        float lg2sum = (lg2_approx(pa) + lg2_approx(pc)) +
                       (lg2_approx(pd) + lg2_approx(pe));

        #pragma unroll
        for (int s = 16; s; s >>= 1)
            lg2sum += __shfl_down_sync(0xffffffffu, lg2sum, s);
        if (lane == 0) s_lg2[wid] = lg2sum;
    } else {
        // ============ label-half: scan + exp, named barrier only ==========
        const int* p = cut_label + (size_t)b * S_LEN + sub * 32;
        U8 lA = ldg_u8_stream(p);
        U8 lB = ldg_u8_stream(p + 8);
        U8 lC = ldg_u8_stream(p + 16);
        U8 lD = ldg_u8_stream(p + 24);

        unsigned mask = 0;
        #pragma unroll
        for (int j = 0; j < 8; j++) mask |= lA.v[j] << j;
        #pragma unroll
        for (int j = 0; j < 8; j++) mask |= lB.v[j] << (j + 8);
        #pragma unroll
        for (int j = 0; j < 8; j++) mask |= lC.v[j] << (j + 16);
        #pragma unroll
        for (int j = 0; j < 8; j++) mask |= lD.v[j] << (j + 24);
        int tsum = __popc(mask);

        int incl = tsum;
        #pragma unroll
        for (int s = 1; s < 32; s <<= 1) {
            int v = __shfl_up_sync(0xffffffffu, incl, s);
            if (lane >= s) incl += v;
        }
        const int lw = wid - 4;                 // 0..3
        if (lane == 31) s_ws[lw] = incl;
        asm volatile("bar.sync 1, 128;" ::: "memory");   // label half only

        // 4-value exclusive offset + total (cheap direct read)
        int w0 = s_ws[0], w1 = s_ws[1], w2 = s_ws[2], w3 = s_ws[3];
        int off = (lw > 0 ? w0 : 0) + (lw > 1 ? w1 : 0) + (lw > 2 ? w2 : 0);
        const float T = (float)(w0 + w1 + w2 + w3);

        // exp(r/tau) = ex2( (c*Cx)/(k+T) ),  Cx = 2/(tau*ln2)
        const float Cx = 2.0f / (0.95f * 0.69314718055994531f);
        float cfx = (float)(off + incl - tsum) * Cx;
        float esum = 0.f;
        float den = (float)(sub * 32) + T + 1.0f;
        #pragma unroll
        for (int j = 0; j < 32; j++) {
            if (mask & (1u << j)) cfx += Cx;
            esum += ex2_approx(__fdividef(cfx, den));
            den += 1.0f;
        }

        #pragma unroll
        for (int s = 16; s; s >>= 1)
            esum += __shfl_down_sync(0xffffffffu, esum, s);
        if (lane == 0) s_es[lw] = esum;
    }

    __syncthreads();   // join halves

    if (t == 0) {
        float e = (s_es[0] + s_es[1]) + (s_es[2] + s_es[3]);
        float l = (s_lg2[0] + s_lg2[1]) + (s_lg2[2] + s_lg2[3]);
        float lsum = l * 0.69314718055994531f;           // lg2 -> ln
        float2 pn = reinterpret_cast<const float2*>(rerank_y)[b];
        float hinge = fmaxf(0.f, pn.y - pn.x + 1.0f);
        float contrib = (hinge - lsum / e) * (1.0f / (float)B_ROWS);

        // L2 atomic accumulate (no fence, no L1 flush)
        float oldv = atomicAdd(&g_accum, contrib);
        unsigned z0 = opaque_zero(__float_as_uint(oldv));
        unsigned rank = atomicAdd(&g_count, 1u + z0);

        if (rank == B_ROWS - 1) {
            unsigned z1 = opaque_zero(rank);
            float total = atomicAdd(&g_accum, __uint_as_float(z1));  // += +0.0f
            out[0] = total;
            unsigned z2 = opaque_zero(__float_as_uint(total));
            atomicExch(&g_accum, __uint_as_float(z2));               // = 0.0f
            atomicExch(&g_count, z2);                                // = 0
        }
    }
}

extern "C" void kernel_launch(void* const* d_in, const int* in_sizes, int n_in,
                              void* d_out, int out_size)
{
    const float* rerank_y  = (const float*)d_in[0];   // (8192,1)
    const float* cut_y     = (const float*)d_in[1];   // (4096,4096,1)
    const int*   cut_label = (const int*)d_in[3];     // (4096,4096)
    float* out = (float*)d_out;

    mtcut_row_kernel<<<B_ROWS, BDIM>>>(cut_y, cut_label, rerank_y, out);
}

// round 16
// speedup vs baseline: 1.1735x; 1.1735x over previous
#include <cuda_runtime.h>
#include <cuda_bf16.h>

#define BDIM 256
#define EPT  16                 // elements per thread
#define S_LEN 4096
#define B_ROWS 4096
#define NWARP (BDIM / 32)       // 8
#define GRID 608                // 152 SMs * 4 resident blocks, persistent

__device__ float        g_accum = 0.0f;
__device__ unsigned int g_count = 0;

__device__ __forceinline__ float ex2_approx(float x) {
    float r; asm("ex2.approx.f32 %0, %1;" : "=f"(r) : "f"(x)); return r;
}
__device__ __forceinline__ float lg2_approx(float x) {
    float r; asm("lg2.approx.f32 %0, %1;" : "=f"(r) : "f"(x)); return r;
}
__device__ __forceinline__ unsigned opaque_zero(unsigned v) {
    unsigned z;
    asm volatile("and.b32 %0, %1, 0;" : "=r"(z) : "r"(v));
    return z;
}
__device__ __forceinline__ void prefetch_l2(const void* p) {
    asm volatile("prefetch.global.L2 [%0];" :: "l"(p));
}

struct F8 { float v[8]; };
struct U8 { unsigned v[8]; };
__device__ __forceinline__ F8 ldg_f8_keep(const float* p) {
    F8 r;
    asm volatile(
        "ld.global.nc.L2::evict_last.v8.b32 {%0,%1,%2,%3,%4,%5,%6,%7}, [%8];"
        : "=f"(r.v[0]), "=f"(r.v[1]), "=f"(r.v[2]), "=f"(r.v[3]),
          "=f"(r.v[4]), "=f"(r.v[5]), "=f"(r.v[6]), "=f"(r.v[7])
        : "l"(p));
    return r;
}
__device__ __forceinline__ U8 ldg_u8_stream(const int* p) {
    U8 r;
    asm volatile(
        "ld.global.nc.L2::evict_first.v8.b32 {%0,%1,%2,%3,%4,%5,%6,%7}, [%8];"
        : "=r"(r.v[0]), "=r"(r.v[1]), "=r"(r.v[2]), "=r"(r.v[3]),
          "=r"(r.v[4]), "=r"(r.v[5]), "=r"(r.v[6]), "=r"(r.v[7])
        : "l"(p));
    return r;
}

__global__ __launch_bounds__(BDIM, 4) void mtcut_row_kernel(
    const float* __restrict__ cut_y,
    const int*   __restrict__ cut_label,
    const float* __restrict__ rerank_y,
    float* __restrict__ out)
{
    const int t    = threadIdx.x;
    const int lane = t & 31;
    const int wid  = t >> 5;

    __shared__ float wsum[NWARP];
    __shared__ float woff[NWARP];
    __shared__ float stot;
    __shared__ float se[NWARP], sl[NWARP];

    float block_acc = 0.f;           // meaningful in t0 only

    for (int b = blockIdx.x; b < B_ROWS; b += GRID) {
        const float* yrow = cut_y     + (size_t)b * S_LEN + t * EPT;
        const int*   lrow = cut_label + (size_t)b * S_LEN + t * EPT;

        // 4x 256-bit loads per thread, all destinations live
        F8 yA = ldg_f8_keep(yrow);
        F8 yB = ldg_f8_keep(yrow + 8);
        U8 lA = ldg_u8_stream(lrow);
        U8 lB = ldg_u8_stream(lrow + 8);

        // register-free L2 prefetch of the NEXT row (one 128B line per thread)
        int bn = b + GRID;
        if (bn < B_ROWS) {
            if (t < 128) {
                prefetch_l2((const char*)(cut_y + (size_t)bn * S_LEN) + t * 128);
            } else {
                prefetch_l2((const char*)(cut_label + (size_t)bn * S_LEN) + (t - 128) * 128);
            }
        }

        // sum(log y) = log(prod y): two halves of 8 to dodge underflow
        float pA = ((yA.v[0] * yA.v[1]) * (yA.v[2] * yA.v[3])) *
                   ((yA.v[4] * yA.v[5]) * (yA.v[6] * yA.v[7]));
        float pB = ((yB.v[0] * yB.v[1]) * (yB.v[2] * yB.v[3])) *
                   ((yB.v[4] * yB.v[5]) * (yB.v[6] * yB.v[7]));
        float lg2sum = lg2_approx(pA) + lg2_approx(pB);

        // pack 16 labels into a bit mask
        unsigned mask = 0;
        #pragma unroll
        for (int j = 0; j < 8; j++) mask |= lA.v[j] << j;
        #pragma unroll
        for (int j = 0; j < 8; j++) mask |= lB.v[j] << (j + 8);
        float tsum = (float)__popc(mask);

        // warp inclusive scan (float; exact, <= 4096)
        float incl = tsum;
        #pragma unroll
        for (int d = 1; d < 32; d <<= 1) {
            float v = __shfl_up_sync(0xffffffffu, incl, d);
            if (lane >= d) incl += v;
        }

        if (lane == 31) wsum[wid] = incl;
        __syncthreads();

        // level-2 scan (8-wide) in warp 0, broadcast via smem
        if (wid == 0) {
            float v = (lane < NWARP) ? wsum[lane] : 0.f;
            float s = v;
            #pragma unroll
            for (int d = 1; d < NWARP; d <<= 1) {
                float u = __shfl_up_sync(0xffffffffu, s, d);
                if (lane >= d) s += u;
            }
            if (lane < NWARP) woff[lane] = s - v;
            if (lane == NWARP - 1) stot = s;
        }
        __syncthreads();

        const float T = stot;
        const float Cx = 2.0f / (0.95f * 0.69314718055994531f);
        float cfx = (woff[wid] + (incl - tsum)) * Cx;
        float esum = 0.f;
        float den = (float)(t * EPT) + T + 1.0f;
        #pragma unroll
        for (int j = 0; j < EPT; j++) {
            if (mask & (1u << j)) cfx += Cx;
            esum += ex2_approx(__fdividef(cfx, den));
            den += 1.0f;
        }

        // block reduce esum, lg2sum
        #pragma unroll
        for (int d = 16; d; d >>= 1) {
            esum   += __shfl_down_sync(0xffffffffu, esum, d);
            lg2sum += __shfl_down_sync(0xffffffffu, lg2sum, d);
        }
        if (lane == 0) { se[wid] = esum; sl[wid] = lg2sum; }
        __syncthreads();

        if (t == 0) {
            float e = 0.f, l = 0.f;
            #pragma unroll
            for (int w = 0; w < NWARP; w++) { e += se[w]; l += sl[w]; }
            float lsum = l * 0.69314718055994531f;
            float2 pn = reinterpret_cast<const float2*>(rerank_y)[b];
            float hinge = fmaxf(0.f, pn.y - pn.x + 1.0f);
            block_acc += hinge - lsum / e;
        }
        // next iteration's wsum write is ordered by the syncs above
    }

    if (t == 0) {
        float contrib = block_acc * (1.0f / (float)B_ROWS);

        float oldv = atomicAdd(&g_accum, contrib);
        unsigned z0 = opaque_zero(__float_as_uint(oldv));
        unsigned rank = atomicAdd(&g_count, 1u + z0);

        if (rank == GRID - 1) {
            unsigned z1 = opaque_zero(rank);
            float total = atomicAdd(&g_accum, __uint_as_float(z1));  // += +0.0f
            out[0] = total;
            unsigned z2 = opaque_zero(__float_as_uint(total));
            atomicExch(&g_accum, __uint_as_float(z2));               // = 0.0f
            atomicExch(&g_count, z2);                                // = 0
        }
    }
}

extern "C" void kernel_launch(void* const* d_in, const int* in_sizes, int n_in,
                              void* d_out, int out_size)
{
    const float* rerank_y  = (const float*)d_in[0];   // (8192,1)
    const float* cut_y     = (const float*)d_in[1];   // (4096,4096,1)
    const int*   cut_label = (const int*)d_in[3];     // (4096,4096)
    float* out = (float*)d_out;

    mtcut_row_kernel<<<GRID, BDIM>>>(cut_y, cut_label, rerank_y, out);
}

// round 17
// speedup vs baseline: 1.2778x; 1.0889x over previous
#include <cuda_runtime.h>
#include <cuda_bf16.h>

#define BDIM 256
#define EPT  16                 // elements per thread
#define S_LEN 4096
#define B_ROWS 4096
#define NWARP (BDIM / 32)       // 8

__device__ float        g_accum = 0.0f;
__device__ unsigned int g_count = 0;

__device__ __forceinline__ float ex2_approx(float x) {
    float r; asm("ex2.approx.f32 %0, %1;" : "=f"(r) : "f"(x)); return r;
}
__device__ __forceinline__ float lg2_approx(float x) {
    float r; asm("lg2.approx.f32 %0, %1;" : "=f"(r) : "f"(x)); return r;
}
__device__ __forceinline__ float rcp_approx(float x) {
    float r; asm("rcp.approx.f32 %0, %1;" : "=f"(r) : "f"(x)); return r;
}
__device__ __forceinline__ unsigned opaque_zero(unsigned v) {
    unsigned z;
    asm volatile("and.b32 %0, %1, 0;" : "=r"(z) : "r"(v));
    return z;
}

struct F8 { float v[8]; };
struct U8 { unsigned v[8]; };
__device__ __forceinline__ F8 ldg_f8_keep(const float* p) {
    F8 r;
    asm volatile(
        "ld.global.nc.L2::evict_last.v8.b32 {%0,%1,%2,%3,%4,%5,%6,%7}, [%8];"
        : "=f"(r.v[0]), "=f"(r.v[1]), "=f"(r.v[2]), "=f"(r.v[3]),
          "=f"(r.v[4]), "=f"(r.v[5]), "=f"(r.v[6]), "=f"(r.v[7])
        : "l"(p));
    return r;
}
__device__ __forceinline__ U8 ldg_u8_stream(const int* p) {
    U8 r;
    asm volatile(
        "ld.global.nc.L2::evict_first.v8.b32 {%0,%1,%2,%3,%4,%5,%6,%7}, [%8];"
        : "=r"(r.v[0]), "=r"(r.v[1]), "=r"(r.v[2]), "=r"(r.v[3]),
          "=r"(r.v[4]), "=r"(r.v[5]), "=r"(r.v[6]), "=r"(r.v[7])
        : "l"(p));
    return r;
}

__global__ __launch_bounds__(BDIM, 4) void mtcut_row_kernel(
    const float* __restrict__ cut_y,
    const int*   __restrict__ cut_label,
    const float* __restrict__ rerank_y,
    float* __restrict__ out)
{
    const int b    = blockIdx.x;
    const int t    = threadIdx.x;
    const int lane = t & 31;
    const int wid  = t >> 5;

    const float* yrow = cut_y     + (size_t)b * S_LEN + t * EPT;
    const int*   lrow = cut_label + (size_t)b * S_LEN + t * EPT;

    // 4x 256-bit loads per thread (2 y + 2 label), all destinations live
    F8 yA = ldg_f8_keep(yrow);
    F8 yB = ldg_f8_keep(yrow + 8);
    U8 lA = ldg_u8_stream(lrow);
    U8 lB = ldg_u8_stream(lrow + 8);

    // sum(log y) = log(prod y): two halves of 8 to dodge underflow
    // (y in (1e-4,1): 8-value product >= 1e-32 > FLT_MIN).
    float pA = ((yA.v[0] * yA.v[1]) * (yA.v[2] * yA.v[3])) *
               ((yA.v[4] * yA.v[5]) * (yA.v[6] * yA.v[7]));
    float pB = ((yB.v[0] * yB.v[1]) * (yB.v[2] * yB.v[3])) *
               ((yB.v[4] * yB.v[5]) * (yB.v[6] * yB.v[7]));
    float lg2sum = lg2_approx(pA) + lg2_approx(pB);

    // pack 16 labels (0/1) into a bit mask
    unsigned mask = 0;
    #pragma unroll
    for (int j = 0; j < 8; j++) mask |= lA.v[j] << j;
    #pragma unroll
    for (int j = 0; j < 8; j++) mask |= lB.v[j] << (j + 8);
    float tsum = (float)__popc(mask);

    // warp inclusive scan of per-thread sums (float; exact, <= 4096)
    float incl = tsum;
    #pragma unroll
    for (int d = 1; d < 32; d <<= 1) {
        float v = __shfl_up_sync(0xffffffffu, incl, d);
        if (lane >= d) incl += v;
    }

    __shared__ float wsum[NWARP];
    __shared__ float woff[NWARP];
    __shared__ float stot;
    if (lane == 31) wsum[wid] = incl;
    __syncthreads();

    // level-2 scan (8-wide) in warp 0, broadcast via smem
    if (wid == 0) {
        float v = (lane < NWARP) ? wsum[lane] : 0.f;
        float s = v;
        #pragma unroll
        for (int d = 1; d < NWARP; d <<= 1) {
            float u = __shfl_up_sync(0xffffffffu, s, d);
            if (lane >= d) s += u;
        }
        if (lane < NWARP) woff[lane] = s - v;   // exclusive warp offset
        if (lane == NWARP - 1) stot = s;        // row total T
    }
    __syncthreads();

    const float T = stot;
    // exp(r/tau) = ex2( (c*Cx)/(k+T) ),  Cx = 2/(tau*ln2); r=2c/(k+T) is f1
    const float Cx = 2.0f / (0.95f * 0.69314718055994531f);
    float cfx = (woff[wid] + (incl - tsum)) * Cx;   // exclusive prefix * Cx
    float esum = 0.f;
    float den = (float)(t * EPT) + T + 1.0f;

    if (den >= 1024.0f) {
        // ONE rcp, then incremental Newton reciprocal: r <- r*(2 - den*r).
        // Seed rel err <= 1/(den-1) <= 1e-3 -> post-Newton err <= 1e-6.
        float r = rcp_approx(den);
        #pragma unroll
        for (int j = 0; j < EPT; j++) {
            if (mask & (1u << j)) cfx += Cx;
            esum += ex2_approx(cfx * r);
            den += 1.0f;
            r = r * (2.0f - den * r);
        }
    } else {
        // small denominators: exact per-element divide (few threads only)
        #pragma unroll
        for (int j = 0; j < EPT; j++) {
            if (mask & (1u << j)) cfx += Cx;
            esum += ex2_approx(__fdividef(cfx, den));
            den += 1.0f;
        }
    }

    // block reduce esum, lg2sum
    #pragma unroll
    for (int d = 16; d; d >>= 1) {
        esum   += __shfl_down_sync(0xffffffffu, esum, d);
        lg2sum += __shfl_down_sync(0xffffffffu, lg2sum, d);
    }
    __shared__ float se[NWARP], sl[NWARP];
    if (lane == 0) { se[wid] = esum; sl[wid] = lg2sum; }
    __syncthreads();

    if (t == 0) {
        float e = 0.f, l = 0.f;
        #pragma unroll
        for (int w = 0; w < NWARP; w++) { e += se[w]; l += sl[w]; }
        float lsum = l * 0.69314718055994531f;           // lg2 -> ln
        float2 pn = reinterpret_cast<const float2*>(rerank_y)[b];
        float hinge = fmaxf(0.f, pn.y - pn.x + 1.0f);
        float contrib = (hinge - lsum / e) * (1.0f / (float)B_ROWS);

        // L2 atomic accumulate (no fence, no L1 flush)
        float oldv = atomicAdd(&g_accum, contrib);
        unsigned z0 = opaque_zero(__float_as_uint(oldv));
        unsigned rank = atomicAdd(&g_count, 1u + z0);

        if (rank == B_ROWS - 1) {
            unsigned z1 = opaque_zero(rank);
            float total = atomicAdd(&g_accum, __uint_as_float(z1));  // += +0.0f
            out[0] = total;
            unsigned z2 = opaque_zero(__float_as_uint(total));
            atomicExch(&g_accum, __uint_as_float(z2));               // = 0.0f
            atomicExch(&g_count, z2);                                // = 0
        }
    }
}

extern "C" void kernel_launch(void* const* d_in, const int* in_sizes, int n_in,
                              void* d_out, int out_size)
{
    const float* rerank_y  = (const float*)d_in[0];   // (8192,1)
    const float* cut_y     = (const float*)d_in[1];   // (4096,4096,1)
    const int*   cut_label = (const int*)d_in[3];     // (4096,4096)
    float* out = (float*)d_out;

    mtcut_row_kernel<<<B_ROWS, BDIM>>>(cut_y, cut_label, rerank_y, out);
}